// round 2
// baseline (speedup 1.0000x reference)
#include <cuda_runtime.h>

#define S_LEN 512
#define BATCH 8
#define HEADS 8
#define DHEAD 64
#define INDIM 512
#define PH    322                 // 5*D + 2
#define PHP   324                 // padded to 16B multiple
#define PROJ  (HEADS * PH)        // 2576
#define MROWS (S_LEN * BATCH)     // 4096

// ---- scratch (static device memory; no allocation at runtime) ----
__device__ float g_normed[MROWS * INDIM];   // 8 MB
__device__ float g_qkvb[MROWS * PROJ];      // 42 MB
__device__ float g_hs[MROWS * INDIM];       // 8 MB

// ---- packed f32x2 helpers (Blackwell FFMA2: 2 fp32 FMA per instruction) ----
__device__ __forceinline__ unsigned long long fma_f32x2(
    unsigned long long a, unsigned long long b, unsigned long long c)
{
    unsigned long long d;
    asm("fma.rn.f32x2 %0, %1, %2, %3;" : "=l"(d) : "l"(a), "l"(b), "l"(c));
    return d;
}
__device__ __forceinline__ unsigned long long pack_dup(float x)
{
    unsigned long long d;
    asm("mov.b64 %0, {%1, %1};" : "=l"(d) : "f"(x));
    return d;
}
__device__ __forceinline__ void unpack2(unsigned long long v, float& lo, float& hi)
{
    asm("mov.b64 {%0, %1}, %2;" : "=f"(lo), "=f"(hi) : "l"(v));
}

// ============================================================
// Kernel 1: LayerNorm (biased var, eps=1e-5)
// ============================================================
__global__ void __launch_bounds__(256) ln_kernel(
    const float* __restrict__ x,
    const float* __restrict__ gamma,
    const float* __restrict__ beta)
{
    int m = blockIdx.x;
    int t = threadIdx.x;
    const float* row = x + (size_t)m * INDIM;
    float v0 = row[t];
    float v1 = row[t + 256];

    float s = v0 + v1;
    #pragma unroll
    for (int o = 16; o; o >>= 1) s += __shfl_xor_sync(0xffffffffu, s, o);

    __shared__ float red[8];
    __shared__ float red2[8];
    int w = t >> 5, lane = t & 31;
    if (lane == 0) red[w] = s;
    __syncthreads();
    float tot = 0.f;
    #pragma unroll
    for (int i = 0; i < 8; i++) tot += red[i];
    float mean = tot * (1.0f / INDIM);

    float d0 = v0 - mean, d1 = v1 - mean;
    float sq = d0 * d0 + d1 * d1;
    #pragma unroll
    for (int o = 16; o; o >>= 1) sq += __shfl_xor_sync(0xffffffffu, sq, o);
    if (lane == 0) red2[w] = sq;
    __syncthreads();
    float vtot = 0.f;
    #pragma unroll
    for (int i = 0; i < 8; i++) vtot += red2[i];
    float inv = rsqrtf(vtot * (1.0f / INDIM) + 1e-5f);

    g_normed[(size_t)m * INDIM + t]       = d0 * inv * gamma[t]       + beta[t];
    g_normed[(size_t)m * INDIM + t + 256] = d1 * inv * gamma[t + 256] + beta[t + 256];
}

// ============================================================
// Kernel 2/5: fp32 SGEMM via packed f32x2 FMA, C = A * B^T
// BM=BN=128, BK=16, 256 threads, 8x8 outputs per thread.
// ============================================================
template<bool RESID>
__global__ void __launch_bounds__(256) sgemm_nt(
    const float* __restrict__ A,
    const float* __restrict__ Bm,
    float* __restrict__ C,
    const float* __restrict__ resid,
    int Ndim, int Kdim)
{
    const int BM = 128, BN = 128, BK = 16;
    __shared__ float As[BK][BM + 4];
    __shared__ float Bs[BK][BN + 4];

    int tid   = threadIdx.x;
    int mBase = blockIdx.y * BM;
    int nBase = blockIdx.x * BN;
    int tx = tid & 15, ty = tid >> 4;

    int lrow = tid >> 2;
    int lcol = (tid & 3) * 4;

    unsigned long long acc2[8][4];
    #pragma unroll
    for (int i = 0; i < 8; i++)
        #pragma unroll
        for (int j = 0; j < 4; j++) acc2[i][j] = 0ull;

    for (int k0 = 0; k0 < Kdim; k0 += BK) {
        #pragma unroll
        for (int it = 0; it < 2; it++) {
            int row = lrow + it * 64;
            float4 a = *reinterpret_cast<const float4*>(
                A + (size_t)(mBase + row) * Kdim + k0 + lcol);
            As[lcol + 0][row] = a.x; As[lcol + 1][row] = a.y;
            As[lcol + 2][row] = a.z; As[lcol + 3][row] = a.w;

            int nrow = nBase + row;
            float4 bv = make_float4(0.f, 0.f, 0.f, 0.f);
            if (nrow < Ndim)
                bv = *reinterpret_cast<const float4*>(
                    Bm + (size_t)nrow * Kdim + k0 + lcol);
            Bs[lcol + 0][row] = bv.x; Bs[lcol + 1][row] = bv.y;
            Bs[lcol + 2][row] = bv.z; Bs[lcol + 3][row] = bv.w;
        }
        __syncthreads();

        #pragma unroll
        for (int kk = 0; kk < BK; kk++) {
            float4 a0 = *reinterpret_cast<const float4*>(&As[kk][ty * 8]);
            float4 a1 = *reinterpret_cast<const float4*>(&As[kk][ty * 8 + 4]);
            ulonglong2 bq0 = *reinterpret_cast<const ulonglong2*>(&Bs[kk][tx * 8]);
            ulonglong2 bq1 = *reinterpret_cast<const ulonglong2*>(&Bs[kk][tx * 8 + 4]);
            unsigned long long b2[4] = {bq0.x, bq0.y, bq1.x, bq1.y};
            float af[8] = {a0.x, a0.y, a0.z, a0.w, a1.x, a1.y, a1.z, a1.w};
            #pragma unroll
            for (int i = 0; i < 8; i++) {
                unsigned long long ad = pack_dup(af[i]);
                #pragma unroll
                for (int j = 0; j < 4; j++)
                    acc2[i][j] = fma_f32x2(ad, b2[j], acc2[i][j]);
            }
        }
        __syncthreads();
    }

    #pragma unroll
    for (int i = 0; i < 8; i++) {
        int gm = mBase + ty * 8 + i;
        #pragma unroll
        for (int jj = 0; jj < 4; jj++) {
            float lo, hi;
            unpack2(acc2[i][jj], lo, hi);
            int gn = nBase + tx * 8 + jj * 2;
            if (gn < Ndim) {
                float v = lo;
                if (RESID) v += resid[(size_t)gm * Ndim + gn];
                C[(size_t)gm * Ndim + gn] = v;
            }
            if (gn + 1 < Ndim) {
                float v = hi;
                if (RESID) v += resid[(size_t)gm * Ndim + gn + 1];
                C[(size_t)gm * Ndim + gn + 1] = v;
            }
        }
    }
}

// ============================================================
// Kernel 3: per-head activations in place on g_qkvb
// ============================================================
__global__ void __launch_bounds__(256) act_kernel()
{
    int m    = blockIdx.x;
    int wp   = threadIdx.x >> 5;
    int lane = threadIdx.x & 31;
    float* base = g_qkvb + (size_t)m * PROJ + wp * PH;

    const int segs[3] = {0, 64, 192};
    #pragma unroll
    for (int si = 0; si < 3; si++) {
        int seg = segs[si];
        float a  = base[seg + lane];
        float bb = base[seg + 32 + lane];
        float mx = fmaxf(a, bb);
        #pragma unroll
        for (int o = 16; o; o >>= 1) mx = fmaxf(mx, __shfl_xor_sync(0xffffffffu, mx, o));
        float ea = __expf(a - mx);
        float eb = __expf(bb - mx);
        float s2 = ea + eb;
        #pragma unroll
        for (int o = 16; o; o >>= 1) s2 += __shfl_xor_sync(0xffffffffu, s2, o);
        float inv = 1.0f / s2;
        base[seg + lane]      = ea * inv;
        base[seg + 32 + lane] = eb * inv;
    }
    if (lane < 2) {
        float v = base[320 + lane];
        base[320 + lane] = 1.0f / (1.0f + __expf(-v));
    }
}

// ============================================================
// Kernel 4: sequential scan, v2
// 64 CTAs = (b,h); 256 threads; 4 threads per matrix row (16 cols each).
// ONE block barrier per step; softmax computed redundantly per warp;
// e kept in warp-private SMEM strip (syncwarp only); h & inputs double-buffered.
// ============================================================
__device__ __forceinline__ float dot16(const float* a, const float* __restrict__ b)
{
    float s0 = 0.f, s1 = 0.f, s2 = 0.f, s3 = 0.f;
    #pragma unroll
    for (int j = 0; j < 16; j += 4) {
        s0 = fmaf(a[j],     b[j],     s0);
        s1 = fmaf(a[j + 1], b[j + 1], s1);
        s2 = fmaf(a[j + 2], b[j + 2], s2);
        s3 = fmaf(a[j + 3], b[j + 3], s3);
    }
    return (s0 + s1) + (s2 + s3);
}

__global__ void __launch_bounds__(256) scan_kernel()
{
    int bh = blockIdx.x;
    int b = bh >> 3, h = bh & 7;
    int t    = threadIdx.x;
    int i    = t >> 2;        // row 0..63
    int c    = t & 3;         // column quarter
    int lane = t & 31;
    int w    = t >> 5;        // warp 0..7

    __shared__ float buf[2][PHP];
    __shared__ float h_sh[2][64];
    __shared__ float e_sh[8][80];   // per-warp strip; 4 segments of 16, stride 20

    float W[16], R[16];
    #pragma unroll
    for (int j = 0; j < 16; j++) { W[j] = 0.f; R[j] = 0.f; }

    {   // preload step 0
        const float* src = g_qkvb + (size_t)b * PROJ + h * PH;
        buf[0][t] = src[t];
        if (t < PH - 256) buf[0][t + 256] = src[t + 256];
    }
    if (t < 64)  h_sh[0][t] = 0.f;
    if (t < 128) h_sh[1][t & 63] = 0.f;   // harmless init
    __syncthreads();

    const int cofs = c * 16;

    for (int s = 0; s < S_LEN; s++) {
        const float* in = buf[s & 1];
        const float* hb = h_sh[s & 1];

        // ---- prefetch next step's inputs into registers ----
        float p0 = 0.f, p1 = 0.f;
        if (s + 1 < S_LEN) {
            const float* src = g_qkvb + (size_t)((s + 1) * BATCH + b) * PROJ + h * PH;
            p0 = src[t];
            if (t < PH - 256) p1 = src[t + 256];
        }

        // ---- softmax(h_prev): computed redundantly by EVERY warp ----
        float h0 = hb[lane];
        float h1 = hb[lane + 32];
        float mx = fmaxf(h0, h1);
        #pragma unroll
        for (int o = 16; o; o >>= 1) mx = fmaxf(mx, __shfl_xor_sync(0xffffffffu, mx, o));
        float e0 = __expf(h0 - mx);
        float e1 = __expf(h1 - mx);
        float sm = e0 + e1;
        #pragma unroll
        for (int o = 16; o; o >>= 1) sm += __shfl_xor_sync(0xffffffffu, sm, o);
        float invTot = 1.0f / sm;
        // warp-private scatter (segment stride 20 kills bank conflicts on the gather)
        e_sh[w][(lane >> 4) * 20 + (lane & 15)]            = e0;
        e_sh[w][(2 + (lane >> 4)) * 20 + (lane & 15)]      = e1;
        __syncwarp();

        // ---- delta-rule fast weight W ----
        float kreg[16];
        {
            const float4* kp = reinterpret_cast<const float4*>(in + 64 + cofs);
            #pragma unroll
            for (int q4 = 0; q4 < 4; q4++) {
                float4 v = kp[q4];
                kreg[q4 * 4 + 0] = v.x; kreg[q4 * 4 + 1] = v.y;
                kreg[q4 * 4 + 2] = v.z; kreg[q4 * 4 + 3] = v.w;
            }
        }
        float vold = dot16(W, kreg);
        vold += __shfl_xor_sync(0xffffffffu, vold, 1);
        vold += __shfl_xor_sync(0xffffffffu, vold, 2);
        float coef = in[320] * (in[128 + i] - vold);
        #pragma unroll
        for (int j = 0; j < 16; j++) W[j] = fmaf(coef, kreg[j], W[j]);

        float qreg[16];
        {
            const float4* qp = reinterpret_cast<const float4*>(in + cofs);
            #pragma unroll
            for (int q4 = 0; q4 < 4; q4++) {
                float4 v = qp[q4];
                qreg[q4 * 4 + 0] = v.x; qreg[q4 * 4 + 1] = v.y;
                qreg[q4 * 4 + 2] = v.z; qreg[q4 * 4 + 3] = v.w;
            }
        }
        float z = dot16(W, qreg);
        z += __shfl_xor_sync(0xffffffffu, z, 1);
        z += __shfl_xor_sync(0xffffffffu, z, 2);

        // ---- fast RNN R ----
        float rkreg[16];
        {
            const float4* rp = reinterpret_cast<const float4*>(in + 192 + cofs);
            #pragma unroll
            for (int q4 = 0; q4 < 4; q4++) {
                float4 v = rp[q4];
                rkreg[q4 * 4 + 0] = v.x; rkreg[q4 * 4 + 1] = v.y;
                rkreg[q4 * 4 + 2] = v.z; rkreg[q4 * 4 + 3] = v.w;
            }
        }
        float voldR = dot16(R, rkreg);
        voldR += __shfl_xor_sync(0xffffffffu, voldR, 1);
        voldR += __shfl_xor_sync(0xffffffffu, voldR, 2);
        float coefR = in[321] * (in[256 + i] - voldR);
        #pragma unroll
        for (int j = 0; j < 16; j++) R[j] = fmaf(coefR, rkreg[j], R[j]);

        float ereg[16];
        {
            const float4* ep = reinterpret_cast<const float4*>(&e_sh[w][c * 20]);
            #pragma unroll
            for (int q4 = 0; q4 < 4; q4++) {
                float4 v = ep[q4];
                ereg[q4 * 4 + 0] = v.x; ereg[q4 * 4 + 1] = v.y;
                ereg[q4 * 4 + 2] = v.z; ereg[q4 * 4 + 3] = v.w;
            }
        }
        float hd = dot16(R, ereg);
        hd += __shfl_xor_sync(0xffffffffu, hd, 1);
        hd += __shfl_xor_sync(0xffffffffu, hd, 2);
        float hn = z + hd * invTot;

        if (c == 0) {
            h_sh[(s + 1) & 1][i] = hn;
            g_hs[(size_t)(s * BATCH + b) * INDIM + h * DHEAD + i] = hn;
        }

        // commit prefetched inputs
        float* nb = buf[(s & 1) ^ 1];
        nb[t] = p0;
        if (t < PH - 256) nb[t + 256] = p1;
        __syncthreads();   // the ONE barrier per step
    }
}

// ============================================================
// Launch
// ============================================================
extern "C" void kernel_launch(void* const* d_in, const int* in_sizes, int n_in,
                              void* d_out, int out_size)
{
    const float* x      = (const float*)d_in[0];
    const float* W_slow = (const float*)d_in[1];
    const float* W_out  = (const float*)d_in[2];
    const float* gamma  = (const float*)d_in[3];
    const float* betap  = (const float*)d_in[4];
    float* out = (float*)d_out;

    float *p_normed = nullptr, *p_qkvb = nullptr, *p_hs = nullptr;
    cudaGetSymbolAddress((void**)&p_normed, g_normed);
    cudaGetSymbolAddress((void**)&p_qkvb,   g_qkvb);
    cudaGetSymbolAddress((void**)&p_hs,     g_hs);

    // 1. LayerNorm
    ln_kernel<<<MROWS, 256>>>(x, gamma, betap);

    // 2. qkvb = normed @ W_slow^T   (M=4096, N=2576, K=512)
    {
        dim3 grid((PROJ + 127) / 128, MROWS / 128);
        sgemm_nt<false><<<grid, 256>>>(p_normed, W_slow, p_qkvb, nullptr, PROJ, INDIM);
    }

    // 3. softmax / sigmoid activations in place
    act_kernel<<<MROWS, 256>>>();

    // 4. sequential scan -> g_hs
    scan_kernel<<<BATCH * HEADS, 256>>>();

    // 5. out = x + hs @ W_out^T     (M=4096, N=512, K=512)
    {
        dim3 grid(INDIM / 128, MROWS / 128);
        sgemm_nt<true><<<grid, 256>>>(p_hs, W_out, out, x, INDIM, HEADS * DHEAD);
    }
}

// round 4
// speedup vs baseline: 1.2026x; 1.2026x over previous
#include <cuda_runtime.h>

#define S_LEN 512
#define BATCH 8
#define HEADS 8
#define DHEAD 64
#define INDIM 512
#define PH    322                 // 5*D + 2
#define PHP   324                 // padded (16B multiple of floats)
#define PROJ  (HEADS * PH)        // 2576
#define MROWS (S_LEN * BATCH)     // 4096

// ---- scratch (static device memory; no allocation at runtime) ----
__device__ float g_normed[MROWS * INDIM];   // 8 MB
__device__ float g_qkvb[MROWS * PROJ];      // 42 MB
__device__ float g_hs[MROWS * INDIM];       // 8 MB

// ---- packed f32x2 helpers (Blackwell FFMA2) ----
__device__ __forceinline__ unsigned long long fma_f32x2(
    unsigned long long a, unsigned long long b, unsigned long long c)
{
    unsigned long long d;
    asm("fma.rn.f32x2 %0, %1, %2, %3;" : "=l"(d) : "l"(a), "l"(b), "l"(c));
    return d;
}
__device__ __forceinline__ unsigned long long pack_dup(float x)
{
    unsigned long long d;
    asm("mov.b64 %0, {%1, %1};" : "=l"(d) : "f"(x));
    return d;
}
__device__ __forceinline__ void unpack2(unsigned long long v, float& lo, float& hi)
{
    asm("mov.b64 {%0, %1}, %2;" : "=f"(lo), "=f"(hi) : "l"(v));
}

// ============================================================
// Kernel 1: LayerNorm (biased var, eps=1e-5)
// ============================================================
__global__ void __launch_bounds__(256) ln_kernel(
    const float* __restrict__ x,
    const float* __restrict__ gamma,
    const float* __restrict__ beta)
{
    int m = blockIdx.x;
    int t = threadIdx.x;
    const float* row = x + (size_t)m * INDIM;
    float v0 = row[t];
    float v1 = row[t + 256];

    float s = v0 + v1;
    #pragma unroll
    for (int o = 16; o; o >>= 1) s += __shfl_xor_sync(0xffffffffu, s, o);

    __shared__ float red[8];
    __shared__ float red2[8];
    int w = t >> 5, lane = t & 31;
    if (lane == 0) red[w] = s;
    __syncthreads();
    float tot = 0.f;
    #pragma unroll
    for (int i = 0; i < 8; i++) tot += red[i];
    float mean = tot * (1.0f / INDIM);

    float d0 = v0 - mean, d1 = v1 - mean;
    float sq = d0 * d0 + d1 * d1;
    #pragma unroll
    for (int o = 16; o; o >>= 1) sq += __shfl_xor_sync(0xffffffffu, sq, o);
    if (lane == 0) red2[w] = sq;
    __syncthreads();
    float vtot = 0.f;
    #pragma unroll
    for (int i = 0; i < 8; i++) vtot += red2[i];
    float inv = rsqrtf(vtot * (1.0f / INDIM) + 1e-5f);

    g_normed[(size_t)m * INDIM + t]       = d0 * inv * gamma[t]       + beta[t];
    g_normed[(size_t)m * INDIM + t + 256] = d1 * inv * gamma[t + 256] + beta[t + 256];
}

// ============================================================
// Kernel 2/5: fp32 SGEMM via packed f32x2 FMA, C = A * B^T
// ============================================================
template<bool RESID>
__global__ void __launch_bounds__(256) sgemm_nt(
    const float* __restrict__ A,
    const float* __restrict__ Bm,
    float* __restrict__ C,
    const float* __restrict__ resid,
    int Ndim, int Kdim)
{
    const int BM = 128, BN = 128, BK = 16;
    __shared__ float As[BK][BM + 4];
    __shared__ float Bs[BK][BN + 4];

    int tid   = threadIdx.x;
    int mBase = blockIdx.y * BM;
    int nBase = blockIdx.x * BN;
    int tx = tid & 15, ty = tid >> 4;

    int lrow = tid >> 2;
    int lcol = (tid & 3) * 4;

    unsigned long long acc2[8][4];
    #pragma unroll
    for (int i = 0; i < 8; i++)
        #pragma unroll
        for (int j = 0; j < 4; j++) acc2[i][j] = 0ull;

    for (int k0 = 0; k0 < Kdim; k0 += BK) {
        #pragma unroll
        for (int it = 0; it < 2; it++) {
            int row = lrow + it * 64;
            float4 a = *reinterpret_cast<const float4*>(
                A + (size_t)(mBase + row) * Kdim + k0 + lcol);
            As[lcol + 0][row] = a.x; As[lcol + 1][row] = a.y;
            As[lcol + 2][row] = a.z; As[lcol + 3][row] = a.w;

            int nrow = nBase + row;
            float4 bv = make_float4(0.f, 0.f, 0.f, 0.f);
            if (nrow < Ndim)
                bv = *reinterpret_cast<const float4*>(
                    Bm + (size_t)nrow * Kdim + k0 + lcol);
            Bs[lcol + 0][row] = bv.x; Bs[lcol + 1][row] = bv.y;
            Bs[lcol + 2][row] = bv.z; Bs[lcol + 3][row] = bv.w;
        }
        __syncthreads();

        #pragma unroll
        for (int kk = 0; kk < BK; kk++) {
            float4 a0 = *reinterpret_cast<const float4*>(&As[kk][ty * 8]);
            float4 a1 = *reinterpret_cast<const float4*>(&As[kk][ty * 8 + 4]);
            ulonglong2 bq0 = *reinterpret_cast<const ulonglong2*>(&Bs[kk][tx * 8]);
            ulonglong2 bq1 = *reinterpret_cast<const ulonglong2*>(&Bs[kk][tx * 8 + 4]);
            unsigned long long b2[4] = {bq0.x, bq0.y, bq1.x, bq1.y};
            float af[8] = {a0.x, a0.y, a0.z, a0.w, a1.x, a1.y, a1.z, a1.w};
            #pragma unroll
            for (int i = 0; i < 8; i++) {
                unsigned long long ad = pack_dup(af[i]);
                #pragma unroll
                for (int j = 0; j < 4; j++)
                    acc2[i][j] = fma_f32x2(ad, b2[j], acc2[i][j]);
            }
        }
        __syncthreads();
    }

    #pragma unroll
    for (int i = 0; i < 8; i++) {
        int gm = mBase + ty * 8 + i;
        #pragma unroll
        for (int jj = 0; jj < 4; jj++) {
            float lo, hi;
            unpack2(acc2[i][jj], lo, hi);
            int gn = nBase + tx * 8 + jj * 2;
            if (gn < Ndim) {
                float v = lo;
                if (RESID) v += resid[(size_t)gm * Ndim + gn];
                C[(size_t)gm * Ndim + gn] = v;
            }
            if (gn + 1 < Ndim) {
                float v = hi;
                if (RESID) v += resid[(size_t)gm * Ndim + gn + 1];
                C[(size_t)gm * Ndim + gn + 1] = v;
            }
        }
    }
}

// ============================================================
// Kernel 3: per-head activations in place on g_qkvb
// ============================================================
__global__ void __launch_bounds__(256) act_kernel()
{
    int m    = blockIdx.x;
    int wp   = threadIdx.x >> 5;
    int lane = threadIdx.x & 31;
    float* base = g_qkvb + (size_t)m * PROJ + wp * PH;

    const int segs[3] = {0, 64, 192};
    #pragma unroll
    for (int si = 0; si < 3; si++) {
        int seg = segs[si];
        float a  = base[seg + lane];
        float bb = base[seg + 32 + lane];
        float mx = fmaxf(a, bb);
        #pragma unroll
        for (int o = 16; o; o >>= 1) mx = fmaxf(mx, __shfl_xor_sync(0xffffffffu, mx, o));
        float ea = __expf(a - mx);
        float eb = __expf(bb - mx);
        float s2 = ea + eb;
        #pragma unroll
        for (int o = 16; o; o >>= 1) s2 += __shfl_xor_sync(0xffffffffu, s2, o);
        float inv = 1.0f / s2;
        base[seg + lane]      = ea * inv;
        base[seg + 32 + lane] = eb * inv;
    }
    if (lane < 2) {
        float v = base[320 + lane];
        base[320 + lane] = 1.0f / (1.0f + __expf(-v));
    }
}

// ============================================================
// Kernel 4: sequential scan v3b
// 64 CTAs = (b,h); 128 threads (4 warps); 2 threads per row (32 cols each).
// ONE barrier/step; per-warp redundant softmax (shfl max chain);
// early-commit double-buffered inputs (prefetch gets a full step of cover).
// ============================================================
__device__ __forceinline__ float dot32(const float* a, const float* __restrict__ b)
{
    float s0 = 0.f, s1 = 0.f, s2 = 0.f, s3 = 0.f;
    #pragma unroll
    for (int j = 0; j < 32; j += 4) {
        s0 = fmaf(a[j],     b[j],     s0);
        s1 = fmaf(a[j + 1], b[j + 1], s1);
        s2 = fmaf(a[j + 2], b[j + 2], s2);
        s3 = fmaf(a[j + 3], b[j + 3], s3);
    }
    return (s0 + s1) + (s2 + s3);
}

__device__ __forceinline__ void ld32(float* dst, const float* __restrict__ src)
{
    const float4* p = reinterpret_cast<const float4*>(src);
    #pragma unroll
    for (int q = 0; q < 8; q++) {
        float4 v = p[q];
        dst[q * 4 + 0] = v.x; dst[q * 4 + 1] = v.y;
        dst[q * 4 + 2] = v.z; dst[q * 4 + 3] = v.w;
    }
}

__global__ void __launch_bounds__(128) scan_kernel()
{
    int bh = blockIdx.x;
    int b = bh >> 3, h = bh & 7;
    int t    = threadIdx.x;
    int i    = t >> 1;        // row 0..63
    int c    = t & 1;         // column half
    int lane = t & 31;
    int w    = t >> 5;        // warp 0..3

    __shared__ float buf[2][PHP];
    __shared__ float h_sh[2][64];
    __shared__ float e_sh[4][64];   // per-warp strip

    float W[32], R[32];
    #pragma unroll
    for (int j = 0; j < 32; j++) { W[j] = 0.f; R[j] = 0.f; }

    // preload step 0 directly; prefetch step 1 into regs
    {
        const float* src = g_qkvb + (size_t)b * PROJ + h * PH;
        buf[0][t]       = src[t];
        buf[0][t + 128] = src[t + 128];
        if (t < PH - 256) buf[0][t + 256] = src[t + 256];
    }
    float p0, p1, p2 = 0.f;
    {
        const float* src = g_qkvb + (size_t)(BATCH + b) * PROJ + h * PH;
        p0 = src[t];
        p1 = src[t + 128];
        if (t < PH - 256) p2 = src[t + 256];
    }
    if (t < 64) { h_sh[0][t] = 0.f; h_sh[1][t] = 0.f; }
    __syncthreads();

    const int cofs = c * 32;

    for (int s = 0; s < S_LEN; s++) {
        // ---- early-commit prefetched inputs for step s+1 ----
        {
            float* nb = buf[(s + 1) & 1];
            nb[t]       = p0;
            nb[t + 128] = p1;
            if (t < PH - 256) nb[t + 256] = p2;
        }
        // ---- issue prefetch for step s+2 (full step to cover DRAM) ----
        if (s + 2 < S_LEN) {
            const float* src = g_qkvb + (size_t)((s + 2) * BATCH + b) * PROJ + h * PH;
            p0 = src[t];
            p1 = src[t + 128];
            if (t < PH - 256) p2 = src[t + 256];
        }

        const float* in = buf[s & 1];
        const float* hb = h_sh[s & 1];

        // ---- softmax(h_prev): redundant per warp (shfl max chain) ----
        float h0 = hb[lane];
        float h1 = hb[lane + 32];
        float mx = fmaxf(h0, h1);
        #pragma unroll
        for (int o = 16; o; o >>= 1) mx = fmaxf(mx, __shfl_xor_sync(0xffffffffu, mx, o));
        float e0 = __expf(h0 - mx);
        float e1 = __expf(h1 - mx);
        e_sh[w][lane]      = e0;
        e_sh[w][lane + 32] = e1;
        float sm = e0 + e1;                      // sum chain hidden under W branch
        #pragma unroll
        for (int o = 16; o; o >>= 1) sm += __shfl_xor_sync(0xffffffffu, sm, o);
        float invTot = __fdividef(1.0f, sm);
        __syncwarp();

        // ---- delta-rule fast weight W ----
        float kreg[32];
        ld32(kreg, in + 64 + cofs);
        float vold = dot32(W, kreg);
        vold += __shfl_xor_sync(0xffffffffu, vold, 1);
        float coef = in[320] * (in[128 + i] - vold);
        #pragma unroll
        for (int j = 0; j < 32; j++) W[j] = fmaf(coef, kreg[j], W[j]);

        float qreg[32];
        ld32(qreg, in + cofs);
        float z = dot32(W, qreg);
        z += __shfl_xor_sync(0xffffffffu, z, 1);

        // ---- fast RNN R ----
        float rkreg[32];
        ld32(rkreg, in + 192 + cofs);
        float voldR = dot32(R, rkreg);
        voldR += __shfl_xor_sync(0xffffffffu, voldR, 1);
        float coefR = in[321] * (in[256 + i] - voldR);
        #pragma unroll
        for (int j = 0; j < 32; j++) R[j] = fmaf(coefR, rkreg[j], R[j]);

        float ereg[32];
        ld32(ereg, &e_sh[w][cofs]);
        float hd = dot32(R, ereg);
        hd += __shfl_xor_sync(0xffffffffu, hd, 1);
        float hn = z + hd * invTot;

        if (c == 0) {
            h_sh[(s + 1) & 1][i] = hn;
            g_hs[(size_t)(s * BATCH + b) * INDIM + h * DHEAD + i] = hn;
        }
        __syncthreads();   // the ONE barrier per step
    }
}

// ============================================================
// Launch
// ============================================================
extern "C" void kernel_launch(void* const* d_in, const int* in_sizes, int n_in,
                              void* d_out, int out_size)
{
    const float* x      = (const float*)d_in[0];
    const float* W_slow = (const float*)d_in[1];
    const float* W_out  = (const float*)d_in[2];
    const float* gamma  = (const float*)d_in[3];
    const float* betap  = (const float*)d_in[4];
    float* out = (float*)d_out;

    float *p_normed = nullptr, *p_qkvb = nullptr, *p_hs = nullptr;
    cudaGetSymbolAddress((void**)&p_normed, g_normed);
    cudaGetSymbolAddress((void**)&p_qkvb,   g_qkvb);
    cudaGetSymbolAddress((void**)&p_hs,     g_hs);

    // 1. LayerNorm
    ln_kernel<<<MROWS, 256>>>(x, gamma, betap);

    // 2. qkvb = normed @ W_slow^T   (M=4096, N=2576, K=512)
    {
        dim3 grid((PROJ + 127) / 128, MROWS / 128);
        sgemm_nt<false><<<grid, 256>>>(p_normed, W_slow, p_qkvb, nullptr, PROJ, INDIM);
    }

    // 3. softmax / sigmoid activations in place
    act_kernel<<<MROWS, 256>>>();

    // 4. sequential scan -> g_hs
    scan_kernel<<<BATCH * HEADS, 128>>>();

    // 5. out = x + hs @ W_out^T     (M=4096, N=512, K=512)
    {
        dim3 grid(INDIM / 128, MROWS / 128);
        sgemm_nt<true><<<grid, 256>>>(p_hs, W_out, out, x, INDIM, HEADS * DHEAD);
    }
}

// round 6
// speedup vs baseline: 1.3437x; 1.1173x over previous
#include <cuda_runtime.h>
#include <cstdint>

#define S_LEN 512
#define BATCH 8
#define HEADS 8
#define DHEAD 64
#define INDIM 512
#define PH    322                 // 5*D + 2
#define PHP   324
#define PROJ  (HEADS * PH)        // 2576
#define MROWS (S_LEN * BATCH)     // 4096

// ---- scratch (static device memory; no allocation at runtime) ----
__device__ float g_normed[MROWS * INDIM];   // 8 MB
__device__ float g_qkvb[MROWS * PROJ];      // 42 MB
__device__ float g_hs[MROWS * INDIM];       // 8 MB

// fp32 -> tf32 round-to-nearest-even (integer path; no cvt.tf32 dependency)
__device__ __forceinline__ uint32_t f2tf32(float x)
{
    uint32_t u = __float_as_uint(x);
    u = (u + 0xFFFu + ((u >> 13) & 1u)) & 0xFFFFE000u;
    return u;
}

// m16n8k8 tf32 tensor-core MMA (legacy path, valid on plain sm_103 target)
__device__ __forceinline__ void mma_tf32(float* c, const uint32_t* a, const uint32_t* b)
{
    asm volatile(
        "mma.sync.aligned.m16n8k8.row.col.f32.tf32.tf32.f32 "
        "{%0,%1,%2,%3}, {%4,%5,%6,%7}, {%8,%9}, {%0,%1,%2,%3};"
        : "+f"(c[0]), "+f"(c[1]), "+f"(c[2]), "+f"(c[3])
        : "r"(a[0]), "r"(a[1]), "r"(a[2]), "r"(a[3]), "r"(b[0]), "r"(b[1]));
}

// ============================================================
// Kernel 1: LayerNorm (biased var, eps=1e-5)
// ============================================================
__global__ void __launch_bounds__(256) ln_kernel(
    const float* __restrict__ x,
    const float* __restrict__ gamma,
    const float* __restrict__ beta)
{
    int m = blockIdx.x;
    int t = threadIdx.x;
    const float* row = x + (size_t)m * INDIM;
    float v0 = row[t];
    float v1 = row[t + 256];

    float s = v0 + v1;
    #pragma unroll
    for (int o = 16; o; o >>= 1) s += __shfl_xor_sync(0xffffffffu, s, o);

    __shared__ float red[8];
    __shared__ float red2[8];
    int w = t >> 5, lane = t & 31;
    if (lane == 0) red[w] = s;
    __syncthreads();
    float tot = 0.f;
    #pragma unroll
    for (int i = 0; i < 8; i++) tot += red[i];
    float mean = tot * (1.0f / INDIM);

    float d0 = v0 - mean, d1 = v1 - mean;
    float sq = d0 * d0 + d1 * d1;
    #pragma unroll
    for (int o = 16; o; o >>= 1) sq += __shfl_xor_sync(0xffffffffu, sq, o);
    if (lane == 0) red2[w] = sq;
    __syncthreads();
    float vtot = 0.f;
    #pragma unroll
    for (int i = 0; i < 8; i++) vtot += red2[i];
    float inv = rsqrtf(vtot * (1.0f / INDIM) + 1e-5f);

    g_normed[(size_t)m * INDIM + t]       = d0 * inv * gamma[t]       + beta[t];
    g_normed[(size_t)m * INDIM + t + 256] = d1 * inv * gamma[t + 256] + beta[t + 256];
}

// ============================================================
// Kernel 2/5: TF32x3 tensor-core GEMM, C = A * B^T (+resid)
// A[M,K], B[N,K] row-major fp32. BM=BN=128, BK=16, 256 threads.
// 8 warps as 4(m) x 2(n); warp tile 32x64 = 2x8 m16n8 atoms.
// 3-term split per atom: Ah*Bh + Al*Bh + Ah*Bl  (~fp32 accuracy).
// ============================================================
#define TC_BM 128
#define TC_BN 128
#define TC_BK 16

template<bool RESID>
__global__ void __launch_bounds__(256) mma_gemm_nt(
    const float* __restrict__ A,
    const float* __restrict__ Bm,
    float* __restrict__ C,
    const float* __restrict__ resid,
    int Ndim, int Kdim)
{
    __shared__ uint32_t Ah[TC_BM][20], Al[TC_BM][20];
    __shared__ uint32_t Bh[TC_BN][20], Bl[TC_BN][20];

    const int tid    = threadIdx.x;
    const int lane   = tid & 31;
    const int wid    = tid >> 5;
    const int warp_m = wid & 3;       // 0..3
    const int warp_n = wid >> 2;      // 0..1
    const int g      = lane >> 2;     // group 0..7
    const int tq     = lane & 3;      // 0..3
    const int mBase  = blockIdx.y * TC_BM;
    const int nBase  = blockIdx.x * TC_BN;

    const int lrow = tid >> 2;                // 0..63
    const int lc4  = (tid & 3) * 4;           // 0,4,8,12

    float c[2][8][4];
    #pragma unroll
    for (int am = 0; am < 2; am++)
        #pragma unroll
        for (int an = 0; an < 8; an++)
            #pragma unroll
            for (int q = 0; q < 4; q++) c[am][an][q] = 0.f;

    const int NKB = Kdim / TC_BK;

    // prefetch kb=0
    float4 ra[2], rb[2];
    #pragma unroll
    for (int it = 0; it < 2; it++) {
        int row = lrow + it * 64;
        ra[it] = *reinterpret_cast<const float4*>(A + (size_t)(mBase + row) * Kdim + lc4);
        int nrow = nBase + row;
        rb[it] = (nrow < Ndim)
            ? *reinterpret_cast<const float4*>(Bm + (size_t)nrow * Kdim + lc4)
            : make_float4(0.f, 0.f, 0.f, 0.f);
    }

    for (int kb = 0; kb < NKB; kb++) {
        __syncthreads();   // previous compute done before overwrite
        #pragma unroll
        for (int it = 0; it < 2; it++) {
            int row = lrow + it * 64;
            float xs[4] = {ra[it].x, ra[it].y, ra[it].z, ra[it].w};
            uint32_t h4[4], l4[4];
            #pragma unroll
            for (int q = 0; q < 4; q++) {
                h4[q] = f2tf32(xs[q]);
                l4[q] = f2tf32(xs[q] - __uint_as_float(h4[q]));
            }
            *reinterpret_cast<uint4*>(&Ah[row][lc4]) = make_uint4(h4[0], h4[1], h4[2], h4[3]);
            *reinterpret_cast<uint4*>(&Al[row][lc4]) = make_uint4(l4[0], l4[1], l4[2], l4[3]);

            float ys[4] = {rb[it].x, rb[it].y, rb[it].z, rb[it].w};
            #pragma unroll
            for (int q = 0; q < 4; q++) {
                h4[q] = f2tf32(ys[q]);
                l4[q] = f2tf32(ys[q] - __uint_as_float(h4[q]));
            }
            *reinterpret_cast<uint4*>(&Bh[row][lc4]) = make_uint4(h4[0], h4[1], h4[2], h4[3]);
            *reinterpret_cast<uint4*>(&Bl[row][lc4]) = make_uint4(l4[0], l4[1], l4[2], l4[3]);
        }
        __syncthreads();

        // prefetch next kb (overlaps compute)
        if (kb + 1 < NKB) {
            int ko = (kb + 1) * TC_BK;
            #pragma unroll
            for (int it = 0; it < 2; it++) {
                int row = lrow + it * 64;
                ra[it] = *reinterpret_cast<const float4*>(
                    A + (size_t)(mBase + row) * Kdim + ko + lc4);
                int nrow = nBase + row;
                rb[it] = (nrow < Ndim)
                    ? *reinterpret_cast<const float4*>(Bm + (size_t)nrow * Kdim + ko + lc4)
                    : make_float4(0.f, 0.f, 0.f, 0.f);
            }
        }

        #pragma unroll
        for (int ks = 0; ks < 2; ks++) {
            const int kc = ks * 8 + tq;
            uint32_t ah[2][4], al[2][4];
            #pragma unroll
            for (int am = 0; am < 2; am++) {
                int r0 = warp_m * 32 + am * 16 + g;
                ah[am][0] = Ah[r0][kc];     ah[am][1] = Ah[r0 + 8][kc];
                ah[am][2] = Ah[r0][kc + 4]; ah[am][3] = Ah[r0 + 8][kc + 4];
                al[am][0] = Al[r0][kc];     al[am][1] = Al[r0 + 8][kc];
                al[am][2] = Al[r0][kc + 4]; al[am][3] = Al[r0 + 8][kc + 4];
            }
            #pragma unroll
            for (int an = 0; an < 8; an++) {
                int n0 = warp_n * 64 + an * 8 + g;
                uint32_t bh[2] = {Bh[n0][kc], Bh[n0][kc + 4]};
                uint32_t bl[2] = {Bl[n0][kc], Bl[n0][kc + 4]};
                #pragma unroll
                for (int am = 0; am < 2; am++) {
                    mma_tf32(c[am][an], ah[am], bh);
                    mma_tf32(c[am][an], al[am], bh);
                    mma_tf32(c[am][an], ah[am], bl);
                }
            }
        }
    }

    // epilogue
    #pragma unroll
    for (int am = 0; am < 2; am++) {
        int r0 = mBase + warp_m * 32 + am * 16 + g;
        #pragma unroll
        for (int an = 0; an < 8; an++) {
            int col = nBase + warp_n * 64 + an * 8 + 2 * tq;
            if (col < Ndim) {
                float2 v0 = make_float2(c[am][an][0], c[am][an][1]);
                float2 v1 = make_float2(c[am][an][2], c[am][an][3]);
                if (RESID) {
                    float2 q0 = *reinterpret_cast<const float2*>(
                        resid + (size_t)r0 * Ndim + col);
                    float2 q1 = *reinterpret_cast<const float2*>(
                        resid + (size_t)(r0 + 8) * Ndim + col);
                    v0.x += q0.x; v0.y += q0.y;
                    v1.x += q1.x; v1.y += q1.y;
                }
                *reinterpret_cast<float2*>(C + (size_t)r0 * Ndim + col) = v0;
                *reinterpret_cast<float2*>(C + (size_t)(r0 + 8) * Ndim + col) = v1;
            }
        }
    }
}

// ============================================================
// Kernel 3: per-head activations in place on g_qkvb
// ============================================================
__global__ void __launch_bounds__(256) act_kernel()
{
    int m    = blockIdx.x;
    int wp   = threadIdx.x >> 5;
    int lane = threadIdx.x & 31;
    float* base = g_qkvb + (size_t)m * PROJ + wp * PH;

    const int segs[3] = {0, 64, 192};
    #pragma unroll
    for (int si = 0; si < 3; si++) {
        int seg = segs[si];
        float a  = base[seg + lane];
        float bb = base[seg + 32 + lane];
        float mx = fmaxf(a, bb);
        #pragma unroll
        for (int o = 16; o; o >>= 1) mx = fmaxf(mx, __shfl_xor_sync(0xffffffffu, mx, o));
        float ea = __expf(a - mx);
        float eb = __expf(bb - mx);
        float s2 = ea + eb;
        #pragma unroll
        for (int o = 16; o; o >>= 1) s2 += __shfl_xor_sync(0xffffffffu, s2, o);
        float inv = 1.0f / s2;
        base[seg + lane]      = ea * inv;
        base[seg + 32 + lane] = eb * inv;
    }
    if (lane < 2) {
        float v = base[320 + lane];
        base[320 + lane] = 1.0f / (1.0f + __expf(-v));
    }
}

// ============================================================
// Kernel 4: sequential scan v3b (unchanged — 330us measured)
// ============================================================
__device__ __forceinline__ float dot32(const float* a, const float* __restrict__ b)
{
    float s0 = 0.f, s1 = 0.f, s2 = 0.f, s3 = 0.f;
    #pragma unroll
    for (int j = 0; j < 32; j += 4) {
        s0 = fmaf(a[j],     b[j],     s0);
        s1 = fmaf(a[j + 1], b[j + 1], s1);
        s2 = fmaf(a[j + 2], b[j + 2], s2);
        s3 = fmaf(a[j + 3], b[j + 3], s3);
    }
    return (s0 + s1) + (s2 + s3);
}

__device__ __forceinline__ void ld32(float* dst, const float* __restrict__ src)
{
    const float4* p = reinterpret_cast<const float4*>(src);
    #pragma unroll
    for (int q = 0; q < 8; q++) {
        float4 v = p[q];
        dst[q * 4 + 0] = v.x; dst[q * 4 + 1] = v.y;
        dst[q * 4 + 2] = v.z; dst[q * 4 + 3] = v.w;
    }
}

__global__ void __launch_bounds__(128) scan_kernel()
{
    int bh = blockIdx.x;
    int b = bh >> 3, h = bh & 7;
    int t    = threadIdx.x;
    int i    = t >> 1;
    int c    = t & 1;
    int lane = t & 31;
    int w    = t >> 5;

    __shared__ float buf[2][PHP];
    __shared__ float h_sh[2][64];
    __shared__ float e_sh[4][64];

    float W[32], R[32];
    #pragma unroll
    for (int j = 0; j < 32; j++) { W[j] = 0.f; R[j] = 0.f; }

    {
        const float* src = g_qkvb + (size_t)b * PROJ + h * PH;
        buf[0][t]       = src[t];
        buf[0][t + 128] = src[t + 128];
        if (t < PH - 256) buf[0][t + 256] = src[t + 256];
    }
    float p0, p1, p2 = 0.f;
    {
        const float* src = g_qkvb + (size_t)(BATCH + b) * PROJ + h * PH;
        p0 = src[t];
        p1 = src[t + 128];
        if (t < PH - 256) p2 = src[t + 256];
    }
    if (t < 64) { h_sh[0][t] = 0.f; h_sh[1][t] = 0.f; }
    __syncthreads();

    const int cofs = c * 32;

    for (int s = 0; s < S_LEN; s++) {
        {
            float* nb = buf[(s + 1) & 1];
            nb[t]       = p0;
            nb[t + 128] = p1;
            if (t < PH - 256) nb[t + 256] = p2;
        }
        if (s + 2 < S_LEN) {
            const float* src = g_qkvb + (size_t)((s + 2) * BATCH + b) * PROJ + h * PH;
            p0 = src[t];
            p1 = src[t + 128];
            if (t < PH - 256) p2 = src[t + 256];
        }

        const float* in = buf[s & 1];
        const float* hb = h_sh[s & 1];

        float h0 = hb[lane];
        float h1 = hb[lane + 32];
        float mx = fmaxf(h0, h1);
        #pragma unroll
        for (int o = 16; o; o >>= 1) mx = fmaxf(mx, __shfl_xor_sync(0xffffffffu, mx, o));
        float e0 = __expf(h0 - mx);
        float e1 = __expf(h1 - mx);
        e_sh[w][lane]      = e0;
        e_sh[w][lane + 32] = e1;
        float sm = e0 + e1;
        #pragma unroll
        for (int o = 16; o; o >>= 1) sm += __shfl_xor_sync(0xffffffffu, sm, o);
        float invTot = __fdividef(1.0f, sm);
        __syncwarp();

        float kreg[32];
        ld32(kreg, in + 64 + cofs);
        float vold = dot32(W, kreg);
        vold += __shfl_xor_sync(0xffffffffu, vold, 1);
        float coef = in[320] * (in[128 + i] - vold);
        #pragma unroll
        for (int j = 0; j < 32; j++) W[j] = fmaf(coef, kreg[j], W[j]);

        float qreg[32];
        ld32(qreg, in + cofs);
        float z = dot32(W, qreg);
        z += __shfl_xor_sync(0xffffffffu, z, 1);

        float rkreg[32];
        ld32(rkreg, in + 192 + cofs);
        float voldR = dot32(R, rkreg);
        voldR += __shfl_xor_sync(0xffffffffu, voldR, 1);
        float coefR = in[321] * (in[256 + i] - voldR);
        #pragma unroll
        for (int j = 0; j < 32; j++) R[j] = fmaf(coefR, rkreg[j], R[j]);

        float ereg[32];
        ld32(ereg, &e_sh[w][cofs]);
        float hd = dot32(R, ereg);
        hd += __shfl_xor_sync(0xffffffffu, hd, 1);
        float hn = z + hd * invTot;

        if (c == 0) {
            h_sh[(s + 1) & 1][i] = hn;
            g_hs[(size_t)(s * BATCH + b) * INDIM + h * DHEAD + i] = hn;
        }
        __syncthreads();
    }
}

// ============================================================
// Launch
// ============================================================
extern "C" void kernel_launch(void* const* d_in, const int* in_sizes, int n_in,
                              void* d_out, int out_size)
{
    const float* x      = (const float*)d_in[0];
    const float* W_slow = (const float*)d_in[1];
    const float* W_out  = (const float*)d_in[2];
    const float* gamma  = (const float*)d_in[3];
    const float* betap  = (const float*)d_in[4];
    float* out = (float*)d_out;

    float *p_normed = nullptr, *p_qkvb = nullptr, *p_hs = nullptr;
    cudaGetSymbolAddress((void**)&p_normed, g_normed);
    cudaGetSymbolAddress((void**)&p_qkvb,   g_qkvb);
    cudaGetSymbolAddress((void**)&p_hs,     g_hs);

    // 1. LayerNorm
    ln_kernel<<<MROWS, 256>>>(x, gamma, betap);

    // 2. qkvb = normed @ W_slow^T   (M=4096, N=2576, K=512) — tf32x3 mma.sync
    {
        dim3 grid((PROJ + TC_BN - 1) / TC_BN, MROWS / TC_BM);   // 21 x 32
        mma_gemm_nt<false><<<grid, 256>>>(p_normed, W_slow, p_qkvb, nullptr,
                                          PROJ, INDIM);
    }

    // 3. softmax / sigmoid activations in place
    act_kernel<<<MROWS, 256>>>();

    // 4. sequential scan -> g_hs
    scan_kernel<<<BATCH * HEADS, 128>>>();

    // 5. out = x + hs @ W_out^T     (M=4096, N=512, K=512) — tf32x3 mma.sync
    {
        dim3 grid(INDIM / TC_BN, MROWS / TC_BM);                // 4 x 32
        mma_gemm_nt<true><<<grid, 256>>>(p_hs, W_out, out, x,
                                         INDIM, HEADS * DHEAD);
    }
}